// round 10
// baseline (speedup 1.0000x reference)
#include <cuda_runtime.h>
#include <math.h>
#include <stdint.h>

#define BATCH 8
#define CH    64
#define HH    256
#define WW    256
#define HW    65536
#define P     16
#define OC    64
#define NUNSEL 48
#define OUTC  112   // OC + (CH - P)
#define NBINS 256

typedef unsigned long long ull;

// ---------------- device scratch (no allocation allowed) ----------------
__device__ double g_ent[BATCH * CH];
__device__ int    g_sel[BATCH][P];
__device__ int    g_unsel[BATCH][NUNSEL];

// ===================================================================
// Kernel 1: per-(b,c) min/max + privatized 256-bin histogram + entropy
// one block per (b,c). 256 threads x 256 u8 bins = 64KB -> 3 CTAs/SM.
// Binning uses a reciprocal-multiply fast path; lanes whose scaled value
// lands within 2.5e-4 of a bin boundary (>=4x the max fast-path error)
// fall back to the exact IEEE division the reference uses. Bins are
// therefore bit-identical to trunc(256 * fl((x-mn)/den)).
// ===================================================================
__global__ __launch_bounds__(256) void hist_entropy_kernel(const float* __restrict__ x) {
    extern __shared__ unsigned char s_hist[];   // [tid][rot(bin)], 256*256 u8
    __shared__ float  s_mn[256];
    __shared__ float  s_mx[256];
    __shared__ double s_d[256];

    const int bc  = blockIdx.x;          // 0..511
    const int tid = threadIdx.x;
    const float4* xp = (const float4*)(x + (size_t)bc * HW);

    // zero private histograms (65536 u8 = 4096 uint4)
    {
        uint4* h4 = (uint4*)s_hist;
        #pragma unroll
        for (int i = 0; i < 16; i++) h4[tid + i * 256] = make_uint4(0u, 0u, 0u, 0u);
    }

    // ---- pass 1: min/max (2-way unrolled for MLP) ----
    float mn =  3.4e38f, mx = -3.4e38f;
    for (int i = tid; i < HW / 4; i += 512) {
        float4 a = xp[i];
        float4 b = xp[i + 256];
        mn = fminf(mn, fminf(fminf(a.x, a.y), fminf(a.z, a.w)));
        mx = fmaxf(mx, fmaxf(fmaxf(a.x, a.y), fmaxf(a.z, a.w)));
        mn = fminf(mn, fminf(fminf(b.x, b.y), fminf(b.z, b.w)));
        mx = fmaxf(mx, fmaxf(fmaxf(b.x, b.y), fmaxf(b.z, b.w)));
    }
    s_mn[tid] = mn; s_mx[tid] = mx;
    __syncthreads();
    for (int s = 128; s > 0; s >>= 1) {
        if (tid < s) {
            s_mn[tid] = fminf(s_mn[tid], s_mn[tid + s]);
            s_mx[tid] = fmaxf(s_mx[tid], s_mx[tid + s]);
        }
        __syncthreads();
    }
    mn = s_mn[0];
    mx = s_mx[0];

    // ---- pass 2: binning (rcp fast path, exact-div fallback) ----
    const float den  = (mx - mn) + 1e-8f;
    const float rcp  = __fdiv_rn(1.0f, den);      // once per block
    const int rot = tid << 2;
    unsigned char* my = s_hist + tid * NBINS;

    auto binof = [&](float v) -> int {
        const float d = v - mn;
        const float g = __fmul_rn(__fmul_rn(d, rcp), 256.0f);
        int k = (int)g;
        const float fr = g - (float)k;
        if (fr < 2.5e-4f || fr > 0.99975f) {
            // exact path = reference: trunc(256 * fl(d/den))
            k = (int)__fmul_rn(__fdiv_rn(d, den), 256.0f);
        }
        return min(max(k, 0), NBINS - 1);
    };

    for (int i = tid; i < HW / 4; i += 512) {
        float4 va = xp[i];
        float4 vb = xp[i + 256];
        const int b0 = binof(va.x);
        const int b1 = binof(va.y);
        const int b2 = binof(va.z);
        const int b3 = binof(va.w);
        const int b4 = binof(vb.x);
        const int b5 = binof(vb.y);
        const int b6 = binof(vb.z);
        const int b7 = binof(vb.w);
        my[(b0 + rot) & 255]++;
        my[(b1 + rot) & 255]++;
        my[(b2 + rot) & 255]++;
        my[(b3 + rot) & 255]++;
        my[(b4 + rot) & 255]++;
        my[(b5 + rot) & 255]++;
        my[(b6 + rot) & 255]++;
        my[(b7 + rot) & 255]++;
    }
    __syncthreads();

    // ---- flush: count for bin 'tid' = sum over all 256 private (rotated) copies ----
    unsigned int cnt = 0;
    #pragma unroll 8
    for (int t = 0; t < 256; t++)
        cnt += (unsigned int)s_hist[t * NBINS + ((tid + (t << 2)) & 255)];

    // ---- entropy (double; preserves f32-reference ordering with margin) ----
    double h = (cnt > 0) ? (double)cnt : 1e-8;
    s_d[tid] = h;
    __syncthreads();
    for (int s = 128; s > 0; s >>= 1) {
        if (tid < s) s_d[tid] += s_d[tid + s];
        __syncthreads();
    }
    double sum = s_d[0];
    __syncthreads();
    double p = h / sum;
    s_d[tid] = -p * log(p + 1e-8);
    __syncthreads();
    for (int s = 128; s > 0; s >>= 1) {
        if (tid < s) s_d[tid] += s_d[tid + s];
        __syncthreads();
    }
    if (tid == 0) g_ent[bc] = s_d[0];
}

// ===================================================================
// Kernel 2: top-16 per batch (strict >, ties -> lowest index, = jax top_k)
// ===================================================================
__global__ __launch_bounds__(256) void topk_kernel() {
    __shared__ double se[BATCH * CH];
    const int tid = threadIdx.x;
    for (int i = tid; i < BATCH * CH; i += 256) se[i] = g_ent[i];
    __syncthreads();
    if (tid < BATCH) {
        const int b = tid;
        bool used[CH];
        #pragma unroll
        for (int c = 0; c < CH; c++) used[c] = false;
        for (int p = 0; p < P; p++) {
            int best = -1;
            double bv = -1e300;
            for (int c = 0; c < CH; c++) {
                if (!used[c]) {
                    double e = se[b * CH + c];
                    if (e > bv) { bv = e; best = c; }
                }
            }
            g_sel[b][p] = best;
            used[best] = true;
        }
        int j = 0;
        for (int c = 0; c < CH; c++)
            if (!used[c]) g_unsel[b][j++] = c;
    }
}

// ===================================================================
// Kernel 3: copy untouched channels (ascending order) to out[:, 64:112]
// (overlapped with conv on a forked stream — pure DRAM vs pure FMA)
// ===================================================================
__global__ __launch_bounds__(256) void copy_untouched_kernel(const float* __restrict__ x,
                                                             float* __restrict__ out) {
    const int j = blockIdx.y;            // 0..383
    const int b = j / NUNSEL;
    const int u = j - b * NUNSEL;
    const int src_c = g_unsel[b][u];
    const float4* s = (const float4*)(x + ((size_t)(b * CH + src_c)) * HW);
    float4*       d = (float4*)(out + ((size_t)(b * OUTC + OC + u)) * HW);
    const int i = blockIdx.x * 256 + threadIdx.x;   // gridDim.x = 64 -> 16384 f4
    d[i] = s[i];
}

// ===================================================================
// Kernel 4: direct 3x3 conv via packed fma.rn.f32x2, 3 CTAs/SM.
// block = one (batch, 32x16 tile). Each thread: 2 rows x 16 oc.
// smem: input 16ic x 18 x 34 (38.25KB) + one 16-oc weight chunk
// [144][16] (9KB) -> 48384B/CTA -> 3 CTAs/SM; regs capped for occ=3.
// ===================================================================
#define TIN_H 18
#define TIN_W 34
#define SIN_ELEMS (16 * TIN_H * TIN_W)   // 9792
#define SWC_ELEMS (144 * 16)             // 2304 (one 16-oc chunk)
#define CONV_SMEM ((SIN_ELEMS + SWC_ELEMS) * 4)   // 48384

__global__ __launch_bounds__(256, 3) void conv_kernel(const float* __restrict__ x,
                                                      const float* __restrict__ wgt,
                                                      const float* __restrict__ bias,
                                                      float* __restrict__ out) {
    extern __shared__ float smem[];
    float* s_in = smem;                  // [ic][18][34]
    float* s_w  = smem + SIN_ELEMS;      // [(ic*9+ky*3+kx)][16]

    const int b       = blockIdx.y;
    const int tileIdx = blockIdx.x;      // 0..127 : 16 tile-rows x 8 tile-cols
    const int ty0 = (tileIdx >> 3) << 4;
    const int tx0 = (tileIdx & 7) << 5;
    const int tid = threadIdx.x;

    // stage input tile with halo (zero padding at image borders)
    for (int i = tid; i < SIN_ELEMS; i += 256) {
        const int ic = i / (TIN_H * TIN_W);
        const int r  = i - ic * (TIN_H * TIN_W);
        const int yy = r / TIN_W;
        const int xx = r - yy * TIN_W;
        const int gy = ty0 + yy - 1;
        const int gx = tx0 + xx - 1;
        float v = 0.0f;
        if (gy >= 0 && gy < HH && gx >= 0 && gx < WW) {
            const int c = g_sel[b][ic];
            v = __ldg(&x[((size_t)(b * CH + c)) * HW + gy * WW + gx]);
        }
        s_in[i] = v;
    }

    const int tx    = tid & 31;
    const int warp  = tid >> 5;     // 0..7
    const int ybase = warp << 1;    // output rows ybase, ybase+1 (tile-local)

    for (int ocg = 0; ocg < OC; ocg += 16) {
        __syncthreads();   // protect s_w from previous iteration's readers
        // stage this ocg's weights transposed: s_w[r*16 + ol] = wgt[(ocg+ol)*144 + r]
        for (int i = tid; i < SWC_ELEMS; i += 256) {
            const int r  = i >> 4;
            const int ol = i & 15;
            s_w[i] = __ldg(&wgt[(ocg + ol) * 144 + r]);
        }
        __syncthreads();

        // acc[r][o] holds oc = ocg+2o (low) and ocg+2o+1 (high)
        ull acc[2][8];
        {
            const ull* bp = (const ull*)(bias + ocg);   // 8B-aligned
            #pragma unroll
            for (int o = 0; o < 8; o++) {
                const ull bb = __ldg(&bp[o]);
                acc[0][o] = bb;
                acc[1][o] = bb;
            }
        }

        for (int ic = 0; ic < P; ic++) {
            const float* si = s_in + ic * (TIN_H * TIN_W);
            // 4 rows x 3 cols window, duplicate-packed (rows reused across ky)
            ull vinp[4][3];
            #pragma unroll
            for (int j = 0; j < 4; j++) {
                #pragma unroll
                for (int kx = 0; kx < 3; kx++) {
                    const float v = si[(ybase + j) * TIN_W + tx + kx];
                    asm("mov.b64 %0, {%1, %1};" : "=l"(vinp[j][kx]) : "f"(v));
                }
            }
            const float* wb = s_w + ic * 9 * 16;
            #pragma unroll
            for (int ky = 0; ky < 3; ky++) {
                #pragma unroll
                for (int kx = 0; kx < 3; kx++) {
                    // 16 weights (8 f32x2 pairs) via broadcast LDS.128
                    const ulonglong2* wp = (const ulonglong2*)(wb + (ky * 3 + kx) * 16);
                    ulonglong2 w0 = wp[0];
                    ulonglong2 w1 = wp[1];
                    ulonglong2 w2 = wp[2];
                    ulonglong2 w3 = wp[3];
                    const ull w[8] = {w0.x, w0.y, w1.x, w1.y, w2.x, w2.y, w3.x, w3.y};
                    #pragma unroll
                    for (int r = 0; r < 2; r++) {
                        const ull vv = vinp[r + ky][kx];
                        #pragma unroll
                        for (int o = 0; o < 8; o++)
                            asm("fma.rn.f32x2 %0, %1, %2, %0;"
                                : "+l"(acc[r][o]) : "l"(vv), "l"(w[o]));
                    }
                }
            }
        }

        // store (coalesced over tx)
        #pragma unroll
        for (int o = 0; o < 8; o++) {
            #pragma unroll
            for (int r = 0; r < 2; r++) {
                const float2 f = *reinterpret_cast<const float2*>(&acc[r][o]);
                const int gy = ty0 + ybase + r;
                const int gx = tx0 + tx;
                out[((size_t)(b * OUTC + ocg + 2 * o))     * HW + gy * WW + gx] = f.x;
                out[((size_t)(b * OUTC + ocg + 2 * o + 1)) * HW + gy * WW + gx] = f.y;
            }
        }
    }
}

// ===================================================================
extern "C" void kernel_launch(void* const* d_in, const int* in_sizes, int n_in,
                              void* d_out, int out_size) {
    const float* x    = (const float*)d_in[0];   // [8,64,256,256]
    const float* wgt  = (const float*)d_in[1];   // [64,16,3,3]
    const float* bias = (const float*)d_in[2];   // [64]
    float* out = (float*)d_out;                  // [8,112,256,256]

    // Lazy one-time stream/event creation (first call is the uncaptured
    // correctness run; capture sees only launches + event fork/join nodes).
    static cudaStream_t s_side = nullptr;
    static cudaEvent_t  e_fork = nullptr, e_join = nullptr;
    static bool attr_done = false;
    if (!s_side) {
        cudaStreamCreateWithFlags(&s_side, cudaStreamNonBlocking);
        cudaEventCreateWithFlags(&e_fork, cudaEventDisableTiming);
        cudaEventCreateWithFlags(&e_join, cudaEventDisableTiming);
    }
    if (!attr_done) {
        cudaFuncSetAttribute(hist_entropy_kernel,
                             cudaFuncAttributeMaxDynamicSharedMemorySize, 256 * NBINS);
        cudaFuncSetAttribute(conv_kernel,
                             cudaFuncAttributeMaxDynamicSharedMemorySize, CONV_SMEM);
        attr_done = true;
    }

    hist_entropy_kernel<<<BATCH * CH, 256, 256 * NBINS>>>(x);
    topk_kernel<<<1, 256>>>();

    // fork: copy (DRAM-bound) runs concurrently with conv (FMA-bound)
    cudaEventRecord(e_fork, 0);
    cudaStreamWaitEvent(s_side, e_fork, 0);
    copy_untouched_kernel<<<dim3(64, BATCH * NUNSEL), 256, 0, s_side>>>(x, out);
    cudaEventRecord(e_join, s_side);

    conv_kernel<<<dim3(128, BATCH), 256, CONV_SMEM>>>(x, wgt, bias, out);
    cudaStreamWaitEvent(0, e_join, 0);
}

// round 11
// speedup vs baseline: 1.3823x; 1.3823x over previous
#include <cuda_runtime.h>
#include <math.h>
#include <stdint.h>

#define BATCH 8
#define CH    64
#define HH    256
#define WW    256
#define HW    65536
#define P     16
#define OC    64
#define NUNSEL 48
#define OUTC  112   // OC + (CH - P)
#define NBINS 256
#define NCHAN (BATCH * CH)      // 512
#define CHUNKS 4                // chunks per channel for hist/minmax kernels

typedef unsigned long long ull;

// ---------------- device scratch (no allocation allowed) ----------------
__device__ unsigned int g_hist[NCHAN * NBINS];   // global histogram
__device__ unsigned int g_mnk[NCHAN];            // ordered-uint min key
__device__ unsigned int g_mxk[NCHAN];            // ordered-uint max key
__device__ double g_ent[NCHAN];
__device__ int    g_sel[BATCH][P];
__device__ int    g_unsel[BATCH][NUNSEL];

// float <-> totally-ordered uint (monotone; NaN-free data)
__device__ __forceinline__ unsigned fkey(float f) {
    unsigned u = __float_as_uint(f);
    return (u & 0x80000000u) ? ~u : (u | 0x80000000u);
}
__device__ __forceinline__ float funkey(unsigned k) {
    unsigned u = (k & 0x80000000u) ? (k & 0x7FFFFFFFu) : ~k;
    return __uint_as_float(u);
}

// ===================================================================
// K0a: init min/max keys (512 entries each)
// ===================================================================
__global__ void init_keys_kernel() {
    const int i = threadIdx.x;   // 512 threads
    if (i < NCHAN) { g_mnk[i] = 0xFFFFFFFFu; g_mxk[i] = 0u; }
}

// ===================================================================
// K0b: zero global histogram (512*256 u32 = 32768 uint4) — side stream
// ===================================================================
__global__ __launch_bounds__(256) void zero_hist_kernel() {
    uint4* p = (uint4*)g_hist;
    p[blockIdx.x * 256 + threadIdx.x] = make_uint4(0u, 0u, 0u, 0u);   // grid 128
}

// ===================================================================
// K1: per-channel min/max, 4 chunk-blocks per channel (2048 blocks)
// ===================================================================
__global__ __launch_bounds__(256) void minmax_kernel(const float* __restrict__ x) {
    __shared__ float s_mn[8], s_mx[8];
    const int bc    = blockIdx.x >> 2;
    const int chunk = blockIdx.x & 3;
    const int tid   = threadIdx.x;
    const float4* xp = (const float4*)(x + (size_t)bc * HW + chunk * (HW / CHUNKS));

    float mn = 3.4e38f, mx = -3.4e38f;
    #pragma unroll
    for (int j = 0; j < 16; j += 2) {               // 4096 f4 per block
        float4 a = xp[tid + (j    ) * 256];
        float4 b = xp[tid + (j + 1) * 256];
        mn = fminf(mn, fminf(fminf(a.x, a.y), fminf(a.z, a.w)));
        mx = fmaxf(mx, fmaxf(fmaxf(a.x, a.y), fmaxf(a.z, a.w)));
        mn = fminf(mn, fminf(fminf(b.x, b.y), fminf(b.z, b.w)));
        mx = fmaxf(mx, fmaxf(fmaxf(b.x, b.y), fmaxf(b.z, b.w)));
    }
    #pragma unroll
    for (int o = 16; o; o >>= 1) {
        mn = fminf(mn, __shfl_xor_sync(0xFFFFFFFFu, mn, o));
        mx = fmaxf(mx, __shfl_xor_sync(0xFFFFFFFFu, mx, o));
    }
    if ((tid & 31) == 0) { s_mn[tid >> 5] = mn; s_mx[tid >> 5] = mx; }
    __syncthreads();
    if (tid == 0) {
        #pragma unroll
        for (int w = 1; w < 8; w++) { mn = fminf(mn, s_mn[w]); mx = fmaxf(mx, s_mx[w]); }
        atomicMin(&g_mnk[bc], fkey(mn));
        atomicMax(&g_mxk[bc], fkey(mx));
    }
}

// ===================================================================
// K2: binning, 4 chunk-blocks per channel (2048 blocks, 4.6 waves).
// 256 thr x 256 u8 private bins = 64KB smem, 3 CTAs/SM. 64 elems/thread
// so u8 cannot wrap. Rotation bin'=(bin+4*tid)&255 -> conflict-free when
// lanes share a bin. rcp-multiply fast path with exact-div fallback for
// values within 2.5e-4 of a bin boundary (>=6x the fast-path error bound)
// -> bins bit-identical to trunc(256 * fl((x-mn)/den)). Merge via gmem atomics.
// ===================================================================
__global__ __launch_bounds__(256) void hist_kernel(const float* __restrict__ x) {
    extern __shared__ unsigned char s_hist[];   // 256*256 u8
    const int bc    = blockIdx.x >> 2;
    const int chunk = blockIdx.x & 3;
    const int tid   = threadIdx.x;
    const float4* xp = (const float4*)(x + (size_t)bc * HW + chunk * (HW / CHUNKS));

    // zero private histograms (65536 u8 = 4096 uint4)
    {
        uint4* h4 = (uint4*)s_hist;
        #pragma unroll
        for (int i = 0; i < 16; i++) h4[tid + i * 256] = make_uint4(0u, 0u, 0u, 0u);
    }
    const float mn  = funkey(g_mnk[bc]);
    const float mx  = funkey(g_mxk[bc]);
    const float den = (mx - mn) + 1e-8f;
    const float rcp = __fdiv_rn(1.0f, den);
    __syncthreads();

    const int rot = tid << 2;
    unsigned char* my = s_hist + tid * NBINS;

    auto binof = [&](float v) -> int {
        const float d = v - mn;
        const float g = __fmul_rn(__fmul_rn(d, rcp), 256.0f);
        int k = (int)g;
        const float fr = g - (float)k;
        if (fr < 2.5e-4f || fr > 0.99975f) {
            k = (int)__fmul_rn(__fdiv_rn(d, den), 256.0f);   // exact = reference
        }
        return min(max(k, 0), NBINS - 1);
    };

    #pragma unroll 2
    for (int j = 0; j < 16; j += 2) {               // 4096 f4 per block
        float4 a = xp[tid + (j    ) * 256];
        float4 b = xp[tid + (j + 1) * 256];
        const int b0 = binof(a.x), b1 = binof(a.y), b2 = binof(a.z), b3 = binof(a.w);
        const int b4 = binof(b.x), b5 = binof(b.y), b6 = binof(b.z), b7 = binof(b.w);
        my[(b0 + rot) & 255]++;  my[(b1 + rot) & 255]++;
        my[(b2 + rot) & 255]++;  my[(b3 + rot) & 255]++;
        my[(b4 + rot) & 255]++;  my[(b5 + rot) & 255]++;
        my[(b6 + rot) & 255]++;  my[(b7 + rot) & 255]++;
    }
    __syncthreads();

    // flush: bin 'tid' summed over all 256 private (rotated) copies
    unsigned int cnt = 0;
    #pragma unroll 8
    for (int t = 0; t < 256; t++)
        cnt += (unsigned int)s_hist[t * NBINS + ((tid + (t << 2)) & 255)];
    if (cnt) atomicAdd(&g_hist[bc * NBINS + tid], cnt);
}

// ===================================================================
// K3: entropy per channel — warp per channel, no block syncs.
// grid 16 blocks x 256 thr; block handles 32 channels.
// ===================================================================
__global__ __launch_bounds__(256) void entropy_kernel() {
    const int warp = threadIdx.x >> 5;
    const int lane = threadIdx.x & 31;
    #pragma unroll
    for (int k = 0; k < 4; k++) {
        const int ch = blockIdx.x * 32 + warp + k * 8;
        unsigned c8[8];
        #pragma unroll
        for (int j = 0; j < 8; j++) c8[j] = g_hist[ch * NBINS + lane + j * 32];
        double s = 0.0;
        #pragma unroll
        for (int j = 0; j < 8; j++) s += (c8[j] > 0) ? (double)c8[j] : 1e-8;
        #pragma unroll
        for (int o = 16; o; o >>= 1) s += __shfl_xor_sync(0xFFFFFFFFu, s, o);
        double e = 0.0;
        #pragma unroll
        for (int j = 0; j < 8; j++) {
            const double h = (c8[j] > 0) ? (double)c8[j] : 1e-8;
            const double p = h / s;
            e -= p * log(p + 1e-8);
        }
        #pragma unroll
        for (int o = 16; o; o >>= 1) e += __shfl_xor_sync(0xFFFFFFFFu, e, o);
        if (lane == 0) g_ent[ch] = e;
    }
}

// ===================================================================
// K4: top-16 per batch, warp per batch (strict >, ties -> lowest index).
// Lexicographic max on (value, -index) == serial first-max scan.
// ===================================================================
__global__ __launch_bounds__(256) void topk_kernel() {
    const int b    = threadIdx.x >> 5;
    const int lane = threadIdx.x & 31;
    const double v0 = g_ent[b * CH + lane];
    const double v1 = g_ent[b * CH + 32 + lane];
    bool u0 = false, u1 = false;
    for (int p = 0; p < P; p++) {
        double cv = -1e300; int ci = 1 << 20;
        if (!u0) { cv = v0; ci = lane; }
        if (!u1 && (v1 > cv || (v1 == cv && (32 + lane) < ci))) { cv = v1; ci = 32 + lane; }
        #pragma unroll
        for (int o = 16; o; o >>= 1) {
            const double ov = __shfl_down_sync(0xFFFFFFFFu, cv, o);
            const int    oi = __shfl_down_sync(0xFFFFFFFFu, ci, o);
            if (ov > cv || (ov == cv && oi < ci)) { cv = ov; ci = oi; }
        }
        ci = __shfl_sync(0xFFFFFFFFu, ci, 0);
        if (lane == 0) g_sel[b][p] = ci;
        if (ci == lane)      u0 = true;
        if (ci == 32 + lane) u1 = true;
    }
    const unsigned m0 = __ballot_sync(0xFFFFFFFFu, u0);
    const unsigned m1 = __ballot_sync(0xFFFFFFFFu, u1);
    if (lane == 0) {
        int j = 0;
        for (int c = 0; c < CH; c++) {
            const bool used = (c < 32) ? ((m0 >> c) & 1u) : ((m1 >> (c - 32)) & 1u);
            if (!used) g_unsel[b][j++] = c;
        }
    }
}

// ===================================================================
// K5: copy untouched channels (overlapped with conv on side stream)
// ===================================================================
__global__ __launch_bounds__(256) void copy_untouched_kernel(const float* __restrict__ x,
                                                             float* __restrict__ out) {
    const int j = blockIdx.y;            // 0..383
    const int b = j / NUNSEL;
    const int u = j - b * NUNSEL;
    const int src_c = g_unsel[b][u];
    const float4* s = (const float4*)(x + ((size_t)(b * CH + src_c)) * HW);
    float4*       d = (float4*)(out + ((size_t)(b * OUTC + OC + u)) * HW);
    const int i = blockIdx.x * 256 + threadIdx.x;
    d[i] = s[i];
}

// ===================================================================
// K6: direct 3x3 conv via packed fma.rn.f32x2, 3 CTAs/SM (proven R9).
// ===================================================================
#define TIN_H 18
#define TIN_W 34
#define SIN_ELEMS (16 * TIN_H * TIN_W)   // 9792
#define SWC_ELEMS (144 * 16)             // 2304
#define CONV_SMEM ((SIN_ELEMS + SWC_ELEMS) * 4)   // 48384

__global__ __launch_bounds__(256, 3) void conv_kernel(const float* __restrict__ x,
                                                      const float* __restrict__ wgt,
                                                      const float* __restrict__ bias,
                                                      float* __restrict__ out) {
    extern __shared__ float smem[];
    float* s_in = smem;                  // [ic][18][34]
    float* s_w  = smem + SIN_ELEMS;      // [(ic*9+ky*3+kx)][16]

    const int b       = blockIdx.y;
    const int tileIdx = blockIdx.x;      // 16 tile-rows x 8 tile-cols
    const int ty0 = (tileIdx >> 3) << 4;
    const int tx0 = (tileIdx & 7) << 5;
    const int tid = threadIdx.x;

    for (int i = tid; i < SIN_ELEMS; i += 256) {
        const int ic = i / (TIN_H * TIN_W);
        const int r  = i - ic * (TIN_H * TIN_W);
        const int yy = r / TIN_W;
        const int xx = r - yy * TIN_W;
        const int gy = ty0 + yy - 1;
        const int gx = tx0 + xx - 1;
        float v = 0.0f;
        if (gy >= 0 && gy < HH && gx >= 0 && gx < WW) {
            const int c = g_sel[b][ic];
            v = __ldg(&x[((size_t)(b * CH + c)) * HW + gy * WW + gx]);
        }
        s_in[i] = v;
    }

    const int tx    = tid & 31;
    const int warp  = tid >> 5;
    const int ybase = warp << 1;

    for (int ocg = 0; ocg < OC; ocg += 16) {
        __syncthreads();
        for (int i = tid; i < SWC_ELEMS; i += 256) {
            const int r  = i >> 4;
            const int ol = i & 15;
            s_w[i] = __ldg(&wgt[(ocg + ol) * 144 + r]);
        }
        __syncthreads();

        ull acc[2][8];
        {
            const ull* bp = (const ull*)(bias + ocg);
            #pragma unroll
            for (int o = 0; o < 8; o++) {
                const ull bb = __ldg(&bp[o]);
                acc[0][o] = bb;
                acc[1][o] = bb;
            }
        }

        for (int ic = 0; ic < P; ic++) {
            const float* si = s_in + ic * (TIN_H * TIN_W);
            ull vinp[4][3];
            #pragma unroll
            for (int j = 0; j < 4; j++) {
                #pragma unroll
                for (int kx = 0; kx < 3; kx++) {
                    const float v = si[(ybase + j) * TIN_W + tx + kx];
                    asm("mov.b64 %0, {%1, %1};" : "=l"(vinp[j][kx]) : "f"(v));
                }
            }
            const float* wb = s_w + ic * 9 * 16;
            #pragma unroll
            for (int ky = 0; ky < 3; ky++) {
                #pragma unroll
                for (int kx = 0; kx < 3; kx++) {
                    const ulonglong2* wp = (const ulonglong2*)(wb + (ky * 3 + kx) * 16);
                    ulonglong2 w0 = wp[0];
                    ulonglong2 w1 = wp[1];
                    ulonglong2 w2 = wp[2];
                    ulonglong2 w3 = wp[3];
                    const ull w[8] = {w0.x, w0.y, w1.x, w1.y, w2.x, w2.y, w3.x, w3.y};
                    #pragma unroll
                    for (int r = 0; r < 2; r++) {
                        const ull vv = vinp[r + ky][kx];
                        #pragma unroll
                        for (int o = 0; o < 8; o++)
                            asm("fma.rn.f32x2 %0, %1, %2, %0;"
                                : "+l"(acc[r][o]) : "l"(vv), "l"(w[o]));
                    }
                }
            }
        }

        #pragma unroll
        for (int o = 0; o < 8; o++) {
            #pragma unroll
            for (int r = 0; r < 2; r++) {
                const float2 f = *reinterpret_cast<const float2*>(&acc[r][o]);
                const int gy = ty0 + ybase + r;
                const int gx = tx0 + tx;
                out[((size_t)(b * OUTC + ocg + 2 * o))     * HW + gy * WW + gx] = f.x;
                out[((size_t)(b * OUTC + ocg + 2 * o + 1)) * HW + gy * WW + gx] = f.y;
            }
        }
    }
}

// ===================================================================
extern "C" void kernel_launch(void* const* d_in, const int* in_sizes, int n_in,
                              void* d_out, int out_size) {
    const float* x    = (const float*)d_in[0];   // [8,64,256,256]
    const float* wgt  = (const float*)d_in[1];   // [64,16,3,3]
    const float* bias = (const float*)d_in[2];   // [64]
    float* out = (float*)d_out;                  // [8,112,256,256]

    static cudaStream_t s_side = nullptr;
    static cudaEvent_t  e0 = nullptr, ez = nullptr, ef = nullptr, ej = nullptr;
    static bool attr_done = false;
    if (!s_side) {
        cudaStreamCreateWithFlags(&s_side, cudaStreamNonBlocking);
        cudaEventCreateWithFlags(&e0, cudaEventDisableTiming);
        cudaEventCreateWithFlags(&ez, cudaEventDisableTiming);
        cudaEventCreateWithFlags(&ef, cudaEventDisableTiming);
        cudaEventCreateWithFlags(&ej, cudaEventDisableTiming);
    }
    if (!attr_done) {
        cudaFuncSetAttribute(hist_kernel,
                             cudaFuncAttributeMaxDynamicSharedMemorySize, 256 * NBINS);
        cudaFuncSetAttribute(conv_kernel,
                             cudaFuncAttributeMaxDynamicSharedMemorySize, CONV_SMEM);
        attr_done = true;
    }

    // side stream: zero global histogram, overlapped with init+minmax
    cudaEventRecord(e0, 0);
    cudaStreamWaitEvent(s_side, e0, 0);
    zero_hist_kernel<<<128, 256, 0, s_side>>>();
    cudaEventRecord(ez, s_side);

    init_keys_kernel<<<1, 512>>>();
    minmax_kernel<<<NCHAN * CHUNKS, 256>>>(x);
    cudaStreamWaitEvent(0, ez, 0);
    hist_kernel<<<NCHAN * CHUNKS, 256, 256 * NBINS>>>(x);
    entropy_kernel<<<16, 256>>>();
    topk_kernel<<<1, 256>>>();

    // fork: copy (DRAM-bound) concurrent with conv (FMA-bound)
    cudaEventRecord(ef, 0);
    cudaStreamWaitEvent(s_side, ef, 0);
    copy_untouched_kernel<<<dim3(64, BATCH * NUNSEL), 256, 0, s_side>>>(x, out);
    cudaEventRecord(ej, s_side);

    conv_kernel<<<dim3(128, BATCH), 256, CONV_SMEM>>>(x, wgt, bias, out);
    cudaStreamWaitEvent(0, ej, 0);
}